// round 4
// baseline (speedup 1.0000x reference)
#include <cuda_runtime.h>

#define NN 500000
#define EE 8000000
#define BN_EPS 1e-5

// ---------------- scratch (static device memory; no allocation) ----------------
// layout: [0:N) aggU | [N:2N) indeg | [2N:3N) degw | [3N:4N) aggV | [4N:5N) aggM
//         [5N:6N) aggP | [6N:7N) u | [7N:8N) k | [8N:9N) v | [9N:10N) m | [10N:11N) p
__device__ float g_scratch[11 * NN];
__device__ int g_is32;

struct Stats {
    double two_m;
    double Su, Suu, Sk, Skk;
    double Sv, Svv, Svk;
    double Sm, Smm, Smk;
    double Sp, Spp, Spm, Spk;
    double pos;
    double ds[4];
};
__device__ Stats g_stats;

struct Coef {
    float Lu[4], Lv[4], Lk[4], Lp[4], Lm[4], L0[4];
    float ubar, vbar, kbar, pbar, mbar;
};
__device__ Coef g_coef;

__device__ __forceinline__ double warp_red(double v) {
#pragma unroll
    for (int o = 16; o > 0; o >>= 1) v += __shfl_down_sync(0xffffffffu, v, o);
    return v;
}

// Load src/dst indices regardless of whether edge_index is int32 or int64.
__device__ __forceinline__ void load_sd(const void* ei, int e, int is32, int& s, int& d) {
    if (is32) {
        s = __ldg((const int*)ei + e);
        d = __ldg((const int*)ei + EE + e);
    } else {
        s = (int)__ldg((const long long*)ei + e);
        d = (int)__ldg((const long long*)ei + EE + e);
    }
}

// ---------------- dtype detector: int64 interp of int32 data is >= 2^32 ----------------
__global__ void k_detect(const void* ei) {
    const long long* p = (const long long*)ei;
    int bad = 0;
    for (int i = threadIdx.x; i < 4096; i += blockDim.x) {
        long long v = p[i];
        if (v < 0 || v >= (long long)NN) bad = 1;
    }
    bad = __syncthreads_or(bad);
    if (threadIdx.x == 0) g_is32 = bad;
}

// ---------------- zero pass: scratch accumulators + stats (graph-capturable) --------
__global__ void k_zero() {
    int stride = gridDim.x * blockDim.x;
    int tid = blockIdx.x * blockDim.x + threadIdx.x;
    const int ZN = 6 * NN;
    for (int i = tid; i < ZN; i += stride) g_scratch[i] = 0.0f;
    if (tid < (int)(sizeof(Stats) / sizeof(double))) {
        reinterpret_cast<double*>(&g_stats)[tid] = 0.0;
    }
}

// ---------------- edge pass 1: aggU = A*x, indeg = A*1, degw = seg_sum(w, src), two_m ----
__global__ void k_edge1(const void* __restrict__ ei,
                        const float* __restrict__ x,
                        const float* __restrict__ w) {
    float* aggU  = g_scratch;
    float* indeg = g_scratch + NN;
    float* degw  = g_scratch + 2 * NN;
    const int is32 = g_is32;
    double wsum = 0.0;
    int stride = gridDim.x * blockDim.x;
    for (int e = blockIdx.x * blockDim.x + threadIdx.x; e < EE; e += stride) {
        int s, d;
        load_sd(ei, e, is32, s, d);
        float we = __ldg(&w[e]);
        atomicAdd(&aggU[d], __ldg(&x[s]));
        atomicAdd(&indeg[d], 1.0f);
        atomicAdd(&degw[s], we);
        wsum += (double)we;
    }
    wsum = warp_red(wsum);
    if ((threadIdx.x & 31) == 0) atomicAdd(&g_stats.two_m, wsum);
}

// ---------------- node pass 1: u = x + aggU, k = 1 + indeg, stats ----------------
__global__ void k_node1(const float* __restrict__ x) {
    const float* aggU  = g_scratch;
    const float* indeg = g_scratch + NN;
    float* u = g_scratch + 6 * NN;
    float* k = g_scratch + 7 * NN;
    double su = 0, suu = 0, sk = 0, skk = 0;
    int stride = gridDim.x * blockDim.x;
    for (int i = blockIdx.x * blockDim.x + threadIdx.x; i < NN; i += stride) {
        float uv = x[i] + aggU[i];
        float kv = 1.0f + indeg[i];
        u[i] = uv; k[i] = kv;
        su += uv; suu += (double)uv * uv;
        sk += kv; skk += (double)kv * kv;
    }
    su = warp_red(su); suu = warp_red(suu); sk = warp_red(sk); skk = warp_red(skk);
    if ((threadIdx.x & 31) == 0) {
        atomicAdd(&g_stats.Su, su);  atomicAdd(&g_stats.Suu, suu);
        atomicAdd(&g_stats.Sk, sk);  atomicAdd(&g_stats.Skk, skk);
    }
}

// ---------------- edge pass 2: aggV = A*u, aggM = A*k ----------------
__global__ void k_edge2(const void* __restrict__ ei) {
    const float* u = g_scratch + 6 * NN;
    const float* k = g_scratch + 7 * NN;
    float* aggV = g_scratch + 3 * NN;
    float* aggM = g_scratch + 4 * NN;
    const int is32 = g_is32;
    int stride = gridDim.x * blockDim.x;
    for (int e = blockIdx.x * blockDim.x + threadIdx.x; e < EE; e += stride) {
        int s, d;
        load_sd(ei, e, is32, s, d);
        atomicAdd(&aggV[d], __ldg(&u[s]));
        atomicAdd(&aggM[d], __ldg(&k[s]));
    }
}

// ---------------- node pass 2: v = u + aggV, m = k + aggM, stats ----------------
__global__ void k_node2() {
    const float* u = g_scratch + 6 * NN;
    const float* k = g_scratch + 7 * NN;
    const float* aggV = g_scratch + 3 * NN;
    const float* aggM = g_scratch + 4 * NN;
    float* v = g_scratch + 8 * NN;
    float* m = g_scratch + 9 * NN;
    double sv = 0, svv = 0, svk = 0, sm = 0, smm = 0, smk = 0;
    int stride = gridDim.x * blockDim.x;
    for (int i = blockIdx.x * blockDim.x + threadIdx.x; i < NN; i += stride) {
        float kv = k[i];
        float vv = u[i] + aggV[i];
        float mv = kv + aggM[i];
        v[i] = vv; m[i] = mv;
        sv += vv; svv += (double)vv * vv; svk += (double)vv * kv;
        sm += mv; smm += (double)mv * mv; smk += (double)mv * kv;
    }
    sv = warp_red(sv); svv = warp_red(svv); svk = warp_red(svk);
    sm = warp_red(sm); smm = warp_red(smm); smk = warp_red(smk);
    if ((threadIdx.x & 31) == 0) {
        atomicAdd(&g_stats.Sv, sv);  atomicAdd(&g_stats.Svv, svv); atomicAdd(&g_stats.Svk, svk);
        atomicAdd(&g_stats.Sm, sm);  atomicAdd(&g_stats.Smm, smm); atomicAdd(&g_stats.Smk, smk);
    }
}

// ---------------- edge pass 3: aggP = A*v ----------------
__global__ void k_edge3(const void* __restrict__ ei) {
    const float* v = g_scratch + 8 * NN;
    float* aggP = g_scratch + 5 * NN;
    const int is32 = g_is32;
    int stride = gridDim.x * blockDim.x;
    for (int e = blockIdx.x * blockDim.x + threadIdx.x; e < EE; e += stride) {
        int s, d;
        load_sd(ei, e, is32, s, d);
        atomicAdd(&aggP[d], __ldg(&v[s]));
    }
}

// ---------------- node pass 3: p = v + aggP, stats ----------------
__global__ void k_node3() {
    const float* v = g_scratch + 8 * NN;
    const float* aggP = g_scratch + 5 * NN;
    const float* k = g_scratch + 7 * NN;
    const float* m = g_scratch + 9 * NN;
    float* p = g_scratch + 10 * NN;
    double sp = 0, spp = 0, spm = 0, spk = 0;
    int stride = gridDim.x * blockDim.x;
    for (int i = blockIdx.x * blockDim.x + threadIdx.x; i < NN; i += stride) {
        float pv = v[i] + aggP[i];
        p[i] = pv;
        sp += pv; spp += (double)pv * pv;
        spm += (double)pv * m[i]; spk += (double)pv * k[i];
    }
    sp = warp_red(sp); spp = warp_red(spp); spm = warp_red(spm); spk = warp_red(spk);
    if ((threadIdx.x & 31) == 0) {
        atomicAdd(&g_stats.Sp, sp);  atomicAdd(&g_stats.Spp, spp);
        atomicAdd(&g_stats.Spm, spm); atomicAdd(&g_stats.Spk, spk);
    }
}

// ---------------- coefficient kernel (single thread, double precision) ----------------
// All Linear biases cancel through BN's mean subtraction; only bf and the BN be's survive.
__global__ void k_coef(const float* __restrict__ W1a, const float* __restrict__ W1b,
                       const float* __restrict__ W2a, const float* __restrict__ W2b,
                       const float* __restrict__ W3a, const float* __restrict__ W3b,
                       const float* __restrict__ g1, const float* __restrict__ be1,
                       const float* __restrict__ g2, const float* __restrict__ be2,
                       const float* __restrict__ g3, const float* __restrict__ be3,
                       const float* __restrict__ Wf, const float* __restrict__ bf) {
    if (blockIdx.x != 0 || threadIdx.x != 0) return;
    const double Nd = (double)NN;
    double ubar = g_stats.Su / Nd, Vu = g_stats.Suu / Nd - ubar * ubar;
    double vbar = g_stats.Sv / Nd, Vv = g_stats.Svv / Nd - vbar * vbar;
    double kbar = g_stats.Sk / Nd, Vk = g_stats.Skk / Nd - kbar * kbar;
    double pbar = g_stats.Sp / Nd, Vp = g_stats.Spp / Nd - pbar * pbar;
    double mbar = g_stats.Sm / Nd, Vm = g_stats.Smm / Nd - mbar * mbar;
    double Cvk = g_stats.Svk / Nd - vbar * kbar;
    double Cpm = g_stats.Spm / Nd - pbar * mbar;
    double Cpk = g_stats.Spk / Nd - pbar * kbar;
    double Cmk = g_stats.Smk / Nd - mbar * kbar;

    // layer 1: x11 = alpha1*(u - ubar) + be1
    double alpha1[10];
    for (int f = 0; f < 10; f++) {
        double w1 = 0;
        for (int j = 0; j < 10; j++) w1 += (double)W1a[j] * (double)W1b[j * 10 + f];
        alpha1[f] = (double)g1[f] * w1 / sqrt(w1 * w1 * Vu + BN_EPS);
    }
    // layer 2: h2 = a2*v + b2*k (+const);  x12 = A2*(v-vbar) + B2*(k-kbar) + be2
    double z1[10], z2[10];
    for (int t = 0; t < 10; t++) {
        double s1 = 0, s2 = 0;
        for (int j = 0; j < 10; j++) {
            s1 += alpha1[j] * (double)W2a[j * 10 + t];
            s2 += (double)be1[j] * (double)W2a[j * 10 + t];
        }
        z1[t] = s1; z2[t] = s2;
    }
    double A2[10], B2[10];
    for (int f = 0; f < 10; f++) {
        double a2 = 0, e2 = 0;
        for (int t = 0; t < 10; t++) {
            a2 += z1[t] * (double)W2b[t * 10 + f];
            e2 += z2[t] * (double)W2b[t * 10 + f];
        }
        double b2 = e2 - ubar * a2;
        double s = sqrt(a2 * a2 * Vv + b2 * b2 * Vk + 2.0 * a2 * b2 * Cvk + BN_EPS);
        A2[f] = (double)g2[f] * a2 / s;
        B2[f] = (double)g2[f] * b2 / s;
    }
    // layer 3: h3 = a3*p + b3*m + c3*k (+const); x13 = A3*(p-pbar)+B3*(m-mbar)+C3*(k-kbar)+be3
    double za[10], zb[10], zc[10];
    for (int t = 0; t < 10; t++) {
        double s1 = 0, s2 = 0, s3 = 0;
        for (int j = 0; j < 10; j++) {
            s1 += A2[j] * (double)W3a[j * 10 + t];
            s2 += B2[j] * (double)W3a[j * 10 + t];
            s3 += (double)be2[j] * (double)W3a[j * 10 + t];
        }
        za[t] = s1; zb[t] = s2; zc[t] = s3;
    }
    double A3[10], B3[10], C3[10];
    for (int f = 0; f < 10; f++) {
        double a3 = 0, b3 = 0, e3 = 0;
        for (int t = 0; t < 10; t++) {
            a3 += za[t] * (double)W3b[t * 10 + f];
            b3 += zb[t] * (double)W3b[t * 10 + f];
            e3 += zc[t] * (double)W3b[t * 10 + f];
        }
        double c3 = e3 - vbar * a3 - kbar * b3;
        double s = sqrt(a3 * a3 * Vp + b3 * b3 * Vm + c3 * c3 * Vk +
                        2.0 * a3 * b3 * Cpm + 2.0 * a3 * c3 * Cpk + 2.0 * b3 * c3 * Cmk + BN_EPS);
        A3[f] = (double)g3[f] * a3 / s;
        B3[f] = (double)g3[f] * b3 / s;
        C3[f] = (double)g3[f] * c3 / s;
    }
    // logits[i,:] = (u-ub)Lu + (v-vb)Lv + (k-kb)Lk + (p-pb)Lp + (m-mb)Lm + L0
    for (int c = 0; c < 4; c++) {
        double lu = 0, lv = 0, lk = 0, lp = 0, lm = 0, l0 = (double)bf[c];
        for (int f = 0; f < 10; f++) {
            double wf1 = (double)Wf[f * 4 + c];
            double wf2 = (double)Wf[(10 + f) * 4 + c];
            double wf3 = (double)Wf[(20 + f) * 4 + c];
            lu += alpha1[f] * wf1;
            lv += A2[f] * wf2;
            lk += B2[f] * wf2 + C3[f] * wf3;
            lp += A3[f] * wf3;
            lm += B3[f] * wf3;
            l0 += (double)be1[f] * wf1 + (double)be2[f] * wf2 + (double)be3[f] * wf3;
        }
        g_coef.Lu[c] = (float)lu; g_coef.Lv[c] = (float)lv; g_coef.Lk[c] = (float)lk;
        g_coef.Lp[c] = (float)lp; g_coef.Lm[c] = (float)lm; g_coef.L0[c] = (float)l0;
    }
    g_coef.ubar = (float)ubar; g_coef.vbar = (float)vbar; g_coef.kbar = (float)kbar;
    g_coef.pbar = (float)pbar; g_coef.mbar = (float)mbar;
}

// ---------------- node pass 4: logits -> softmax -> s, and ds = deg @ s ----------------
__global__ void k_node4(float* __restrict__ out) {
    const float* u = g_scratch + 6 * NN;
    const float* k = g_scratch + 7 * NN;
    const float* v = g_scratch + 8 * NN;
    const float* m = g_scratch + 9 * NN;
    const float* p = g_scratch + 10 * NN;
    const float* degw = g_scratch + 2 * NN;
    Coef c = g_coef;
    double d0 = 0, d1 = 0, d2 = 0, d3 = 0;
    int stride = gridDim.x * blockDim.x;
    for (int i = blockIdx.x * blockDim.x + threadIdx.x; i < NN; i += stride) {
        float du = u[i] - c.ubar, dv = v[i] - c.vbar, dk = k[i] - c.kbar;
        float dp = p[i] - c.pbar, dm = m[i] - c.mbar;
        float l0 = du * c.Lu[0] + dv * c.Lv[0] + dk * c.Lk[0] + dp * c.Lp[0] + dm * c.Lm[0] + c.L0[0];
        float l1 = du * c.Lu[1] + dv * c.Lv[1] + dk * c.Lk[1] + dp * c.Lp[1] + dm * c.Lm[1] + c.L0[1];
        float l2 = du * c.Lu[2] + dv * c.Lv[2] + dk * c.Lk[2] + dp * c.Lp[2] + dm * c.Lm[2] + c.L0[2];
        float l3 = du * c.Lu[3] + dv * c.Lv[3] + dk * c.Lk[3] + dp * c.Lp[3] + dm * c.Lm[3] + c.L0[3];
        float mx = fmaxf(fmaxf(l0, l1), fmaxf(l2, l3));
        float e0 = expf(l0 - mx), e1 = expf(l1 - mx), e2 = expf(l2 - mx), e3 = expf(l3 - mx);
        float inv = 1.0f / (e0 + e1 + e2 + e3);
        float4 sv = make_float4(e0 * inv, e1 * inv, e2 * inv, e3 * inv);
        reinterpret_cast<float4*>(out)[i] = sv;
        float dw = degw[i];
        d0 += (double)(dw * sv.x); d1 += (double)(dw * sv.y);
        d2 += (double)(dw * sv.z); d3 += (double)(dw * sv.w);
    }
    d0 = warp_red(d0); d1 = warp_red(d1); d2 = warp_red(d2); d3 = warp_red(d3);
    if ((threadIdx.x & 31) == 0) {
        atomicAdd(&g_stats.ds[0], d0); atomicAdd(&g_stats.ds[1], d1);
        atomicAdd(&g_stats.ds[2], d2); atomicAdd(&g_stats.ds[3], d3);
    }
}

// ---------------- edge pass 5: pos = sum_e w_e * dot(s[src], s[dst]) ----------------
__global__ void k_edge5(const void* __restrict__ ei,
                        const float* __restrict__ w,
                        const float* __restrict__ out) {
    const float4* s4 = reinterpret_cast<const float4*>(out);
    const int is32 = g_is32;
    double acc = 0.0;
    int stride = gridDim.x * blockDim.x;
    for (int e = blockIdx.x * blockDim.x + threadIdx.x; e < EE; e += stride) {
        int s, d;
        load_sd(ei, e, is32, s, d);
        float4 a = __ldg(&s4[s]);
        float4 b = __ldg(&s4[d]);
        acc += (double)(__ldg(&w[e]) * (a.x * b.x + a.y * b.y + a.z * b.z + a.w * b.w));
    }
    acc = warp_red(acc);
    if ((threadIdx.x & 31) == 0) atomicAdd(&g_stats.pos, acc);
}

// ---------------- final: q ----------------
__global__ void k_final(float* __restrict__ out) {
    double tm = g_stats.two_m;
    double q = g_stats.pos / tm;
#pragma unroll
    for (int c = 0; c < 4; c++) {
        double d = g_stats.ds[c] / tm;
        q -= d * d;
    }
    out[(size_t)4 * NN] = (float)q;
}

extern "C" void kernel_launch(void* const* d_in, const int* in_sizes, int n_in,
                              void* d_out, int out_size) {
    const float* x = (const float*)d_in[0];
    const void* ei = d_in[1];
    const float* w = (const float*)d_in[2];
    const float* W1a = (const float*)d_in[3];
    const float* W1b = (const float*)d_in[5];
    const float* g1 = (const float*)d_in[7];
    const float* be1 = (const float*)d_in[8];
    const float* W2a = (const float*)d_in[9];
    const float* W2b = (const float*)d_in[11];
    const float* g2 = (const float*)d_in[13];
    const float* be2 = (const float*)d_in[14];
    const float* W3a = (const float*)d_in[15];
    const float* W3b = (const float*)d_in[17];
    const float* g3 = (const float*)d_in[19];
    const float* be3 = (const float*)d_in[20];
    const float* Wf = (const float*)d_in[21];
    const float* bf = (const float*)d_in[22];
    float* out = (float*)d_out;

    const int ET = 256, EB = 1184;   // edge kernels: 148 SMs * 8 blocks
    const int NT = 256, NB = 592;    // node kernels

    k_detect<<<1, 256>>>(ei);
    k_zero<<<NB, NT>>>();
    k_edge1<<<EB, ET>>>(ei, x, w);
    k_node1<<<NB, NT>>>(x);
    k_edge2<<<EB, ET>>>(ei);
    k_node2<<<NB, NT>>>();
    k_edge3<<<EB, ET>>>(ei);
    k_node3<<<NB, NT>>>();
    k_coef<<<1, 32>>>(W1a, W1b, W2a, W2b, W3a, W3b, g1, be1, g2, be2, g3, be3, Wf, bf);
    k_node4<<<NB, NT>>>(out);
    k_edge5<<<EB, ET>>>(ei, w, out);
    k_final<<<1, 1>>>(out);
}

// round 5
// speedup vs baseline: 1.1684x; 1.1684x over previous
#include <cuda_runtime.h>

#define NN 500000
#define EE 8000000
#define BN_EPS 1e-5

// ---------------- scratch (static device memory; no allocation) ----------------
// float layout:
//  [0:2N)   aggUI  (float2: aggU, indeg)   [zeroed]
//  [2N:4N)  aggVM  (float2: aggV, aggM)    [zeroed]
//  [4N:5N)  degw                            [zeroed]
//  [5N:6N)  aggP                            [zeroed]
//  [6N:8N)  uk     (float2: u, k)
//  [8N:9N)  v
//  [9N:10N) m
//  [10N:11N) p
__device__ float g_scratch[11 * NN];
__device__ int2 g_idx[EE];   // packed (src,dst) int32
__device__ int g_is32;

struct Stats {
    double two_m;
    double Su, Suu, Sk, Skk;
    double Sv, Svv, Svk;
    double Sm, Smm, Smk;
    double Sp, Spp, Spm, Spk;
    double pos;
    double ds[4];
};
__device__ Stats g_stats;

struct Coef {
    float Lu[4], Lv[4], Lk[4], Lp[4], Lm[4], L0[4];
    float ubar, vbar, kbar, pbar, mbar;
};
__device__ Coef g_coef;

__device__ __forceinline__ double warp_red(double v) {
#pragma unroll
    for (int o = 16; o > 0; o >>= 1) v += __shfl_down_sync(0xffffffffu, v, o);
    return v;
}

// vector reduction: one 8B atomic add of {a,b} (sm_90+)
__device__ __forceinline__ void red_add_v2(float2* addr, float a, float b) {
    asm volatile("red.global.add.v2.f32 [%0], {%1, %2};"
                 :: "l"(addr), "f"(a), "f"(b) : "memory");
}

// ---------------- dtype detector: int64 interp of int32 data is >= 2^32 ----------------
__global__ void k_detect(const void* ei) {
    const long long* p = (const long long*)ei;
    int bad = 0;
    for (int i = threadIdx.x; i < 4096; i += blockDim.x) {
        long long v = p[i];
        if (v < 0 || v >= (long long)NN) bad = 1;
    }
    bad = __syncthreads_or(bad);
    if (threadIdx.x == 0) g_is32 = bad;
}

// ---------------- zero pass ----------------
__global__ void k_zero() {
    int stride = gridDim.x * blockDim.x;
    int tid = blockIdx.x * blockDim.x + threadIdx.x;
    const int ZN = 6 * NN;
    float4* z4 = reinterpret_cast<float4*>(g_scratch);
    const int nz = ZN / 4;
    for (int i = tid; i < nz; i += stride) z4[i] = make_float4(0.f, 0.f, 0.f, 0.f);
    if (tid < (int)(sizeof(Stats) / sizeof(double))) {
        reinterpret_cast<double*>(&g_stats)[tid] = 0.0;
    }
}

// ------- edge pass 1: aggU += x[s], indeg += 1 (v2 red), degw[s] += w, two_m; pack idx -------
__global__ void k_edge1(const void* __restrict__ ei,
                        const float* __restrict__ x,
                        const float* __restrict__ w) {
    float2* aggUI = reinterpret_cast<float2*>(g_scratch);
    float* degw = g_scratch + 4 * NN;
    const int is32 = g_is32;
    double wsum = 0.0;
    const int NQ = EE / 4;
    int stride = gridDim.x * blockDim.x;
    for (int q = blockIdx.x * blockDim.x + threadIdx.x; q < NQ; q += stride) {
        int s[4], d[4];
        if (is32) {
            int4 S = __ldg(reinterpret_cast<const int4*>(ei) + q);
            int4 D = __ldg(reinterpret_cast<const int4*>((const int*)ei + EE) + q);
            s[0] = S.x; s[1] = S.y; s[2] = S.z; s[3] = S.w;
            d[0] = D.x; d[1] = D.y; d[2] = D.z; d[3] = D.w;
        } else {
            const longlong2* p = reinterpret_cast<const longlong2*>(ei);
            longlong2 a0 = __ldg(p + 2 * q), a1 = __ldg(p + 2 * q + 1);
            longlong2 b0 = __ldg(p + EE / 2 + 2 * q), b1 = __ldg(p + EE / 2 + 2 * q + 1);
            s[0] = (int)a0.x; s[1] = (int)a0.y; s[2] = (int)a1.x; s[3] = (int)a1.y;
            d[0] = (int)b0.x; d[1] = (int)b0.y; d[2] = (int)b1.x; d[3] = (int)b1.y;
        }
        // pack idx as int4 pairs {s0,d0,s1,d1},{s2,d2,s3,d3}
        reinterpret_cast<int4*>(g_idx)[2 * q]     = make_int4(s[0], d[0], s[1], d[1]);
        reinterpret_cast<int4*>(g_idx)[2 * q + 1] = make_int4(s[2], d[2], s[3], d[3]);
        float4 wv = __ldg(reinterpret_cast<const float4*>(w) + q);
        float xs0 = __ldg(x + s[0]);
        float xs1 = __ldg(x + s[1]);
        float xs2 = __ldg(x + s[2]);
        float xs3 = __ldg(x + s[3]);
        red_add_v2(&aggUI[d[0]], xs0, 1.0f);
        red_add_v2(&aggUI[d[1]], xs1, 1.0f);
        red_add_v2(&aggUI[d[2]], xs2, 1.0f);
        red_add_v2(&aggUI[d[3]], xs3, 1.0f);
        atomicAdd(&degw[s[0]], wv.x);
        atomicAdd(&degw[s[1]], wv.y);
        atomicAdd(&degw[s[2]], wv.z);
        atomicAdd(&degw[s[3]], wv.w);
        wsum += (double)((wv.x + wv.y) + (wv.z + wv.w));
    }
    wsum = warp_red(wsum);
    if ((threadIdx.x & 31) == 0) atomicAdd(&g_stats.two_m, wsum);
}

// ---------------- node pass 1: u = x + aggU, k = 1 + indeg, stats ----------------
__global__ void k_node1(const float* __restrict__ x) {
    const float2* aggUI = reinterpret_cast<const float2*>(g_scratch);
    float2* uk = reinterpret_cast<float2*>(g_scratch + 6 * NN);
    double su = 0, suu = 0, sk = 0, skk = 0;
    int stride = gridDim.x * blockDim.x;
    for (int i = blockIdx.x * blockDim.x + threadIdx.x; i < NN; i += stride) {
        float2 ai = aggUI[i];
        float uv = x[i] + ai.x;
        float kv = 1.0f + ai.y;
        uk[i] = make_float2(uv, kv);
        su += uv; suu += (double)uv * uv;
        sk += kv; skk += (double)kv * kv;
    }
    su = warp_red(su); suu = warp_red(suu); sk = warp_red(sk); skk = warp_red(skk);
    if ((threadIdx.x & 31) == 0) {
        atomicAdd(&g_stats.Su, su);  atomicAdd(&g_stats.Suu, suu);
        atomicAdd(&g_stats.Sk, sk);  atomicAdd(&g_stats.Skk, skk);
    }
}

// ---------------- edge pass 2: aggV += u[s], aggM += k[s]  (one v2 red) ----------------
__global__ void k_edge2() {
    const float2* uk = reinterpret_cast<const float2*>(g_scratch + 6 * NN);
    float2* aggVM = reinterpret_cast<float2*>(g_scratch + 2 * NN);
    const int NQ = EE / 4;
    int stride = gridDim.x * blockDim.x;
    for (int q = blockIdx.x * blockDim.x + threadIdx.x; q < NQ; q += stride) {
        int4 a = __ldg(reinterpret_cast<const int4*>(g_idx) + 2 * q);
        int4 b = __ldg(reinterpret_cast<const int4*>(g_idx) + 2 * q + 1);
        float2 u0 = __ldg(&uk[a.x]);
        float2 u1 = __ldg(&uk[a.z]);
        float2 u2 = __ldg(&uk[b.x]);
        float2 u3 = __ldg(&uk[b.z]);
        red_add_v2(&aggVM[a.y], u0.x, u0.y);
        red_add_v2(&aggVM[a.w], u1.x, u1.y);
        red_add_v2(&aggVM[b.y], u2.x, u2.y);
        red_add_v2(&aggVM[b.w], u3.x, u3.y);
    }
}

// ---------------- node pass 2: v = u + aggV, m = k + aggM, stats ----------------
__global__ void k_node2() {
    const float2* uk = reinterpret_cast<const float2*>(g_scratch + 6 * NN);
    const float2* aggVM = reinterpret_cast<const float2*>(g_scratch + 2 * NN);
    float* v = g_scratch + 8 * NN;
    float* m = g_scratch + 9 * NN;
    double sv = 0, svv = 0, svk = 0, sm = 0, smm = 0, smk = 0;
    int stride = gridDim.x * blockDim.x;
    for (int i = blockIdx.x * blockDim.x + threadIdx.x; i < NN; i += stride) {
        float2 ui = uk[i];
        float2 am = aggVM[i];
        float vv = ui.x + am.x;
        float mv = ui.y + am.y;
        v[i] = vv; m[i] = mv;
        sv += vv; svv += (double)vv * vv; svk += (double)vv * ui.y;
        sm += mv; smm += (double)mv * mv; smk += (double)mv * ui.y;
    }
    sv = warp_red(sv); svv = warp_red(svv); svk = warp_red(svk);
    sm = warp_red(sm); smm = warp_red(smm); smk = warp_red(smk);
    if ((threadIdx.x & 31) == 0) {
        atomicAdd(&g_stats.Sv, sv);  atomicAdd(&g_stats.Svv, svv); atomicAdd(&g_stats.Svk, svk);
        atomicAdd(&g_stats.Sm, sm);  atomicAdd(&g_stats.Smm, smm); atomicAdd(&g_stats.Smk, smk);
    }
}

// ---------------- edge pass 3: aggP += v[s] ----------------
__global__ void k_edge3() {
    const float* v = g_scratch + 8 * NN;
    float* aggP = g_scratch + 5 * NN;
    const int NQ = EE / 4;
    int stride = gridDim.x * blockDim.x;
    for (int q = blockIdx.x * blockDim.x + threadIdx.x; q < NQ; q += stride) {
        int4 a = __ldg(reinterpret_cast<const int4*>(g_idx) + 2 * q);
        int4 b = __ldg(reinterpret_cast<const int4*>(g_idx) + 2 * q + 1);
        float v0 = __ldg(v + a.x);
        float v1 = __ldg(v + a.z);
        float v2 = __ldg(v + b.x);
        float v3 = __ldg(v + b.z);
        atomicAdd(&aggP[a.y], v0);
        atomicAdd(&aggP[a.w], v1);
        atomicAdd(&aggP[b.y], v2);
        atomicAdd(&aggP[b.w], v3);
    }
}

// ---------------- node pass 3: p = v + aggP, stats ----------------
__global__ void k_node3() {
    const float* v = g_scratch + 8 * NN;
    const float* aggP = g_scratch + 5 * NN;
    const float2* uk = reinterpret_cast<const float2*>(g_scratch + 6 * NN);
    const float* m = g_scratch + 9 * NN;
    float* p = g_scratch + 10 * NN;
    double sp = 0, spp = 0, spm = 0, spk = 0;
    int stride = gridDim.x * blockDim.x;
    for (int i = blockIdx.x * blockDim.x + threadIdx.x; i < NN; i += stride) {
        float pv = v[i] + aggP[i];
        p[i] = pv;
        sp += pv; spp += (double)pv * pv;
        spm += (double)pv * m[i]; spk += (double)pv * uk[i].y;
    }
    sp = warp_red(sp); spp = warp_red(spp); spm = warp_red(spm); spk = warp_red(spk);
    if ((threadIdx.x & 31) == 0) {
        atomicAdd(&g_stats.Sp, sp);  atomicAdd(&g_stats.Spp, spp);
        atomicAdd(&g_stats.Spm, spm); atomicAdd(&g_stats.Spk, spk);
    }
}

// ---------------- coefficient kernel (single thread, double precision) ----------------
__global__ void k_coef(const float* __restrict__ W1a, const float* __restrict__ W1b,
                       const float* __restrict__ W2a, const float* __restrict__ W2b,
                       const float* __restrict__ W3a, const float* __restrict__ W3b,
                       const float* __restrict__ g1, const float* __restrict__ be1,
                       const float* __restrict__ g2, const float* __restrict__ be2,
                       const float* __restrict__ g3, const float* __restrict__ be3,
                       const float* __restrict__ Wf, const float* __restrict__ bf) {
    if (blockIdx.x != 0 || threadIdx.x != 0) return;
    const double Nd = (double)NN;
    double ubar = g_stats.Su / Nd, Vu = g_stats.Suu / Nd - ubar * ubar;
    double vbar = g_stats.Sv / Nd, Vv = g_stats.Svv / Nd - vbar * vbar;
    double kbar = g_stats.Sk / Nd, Vk = g_stats.Skk / Nd - kbar * kbar;
    double pbar = g_stats.Sp / Nd, Vp = g_stats.Spp / Nd - pbar * pbar;
    double mbar = g_stats.Sm / Nd, Vm = g_stats.Smm / Nd - mbar * mbar;
    double Cvk = g_stats.Svk / Nd - vbar * kbar;
    double Cpm = g_stats.Spm / Nd - pbar * mbar;
    double Cpk = g_stats.Spk / Nd - pbar * kbar;
    double Cmk = g_stats.Smk / Nd - mbar * kbar;

    double alpha1[10];
    for (int f = 0; f < 10; f++) {
        double w1 = 0;
        for (int j = 0; j < 10; j++) w1 += (double)W1a[j] * (double)W1b[j * 10 + f];
        alpha1[f] = (double)g1[f] * w1 / sqrt(w1 * w1 * Vu + BN_EPS);
    }
    double z1[10], z2[10];
    for (int t = 0; t < 10; t++) {
        double s1 = 0, s2 = 0;
        for (int j = 0; j < 10; j++) {
            s1 += alpha1[j] * (double)W2a[j * 10 + t];
            s2 += (double)be1[j] * (double)W2a[j * 10 + t];
        }
        z1[t] = s1; z2[t] = s2;
    }
    double A2[10], B2[10];
    for (int f = 0; f < 10; f++) {
        double a2 = 0, e2 = 0;
        for (int t = 0; t < 10; t++) {
            a2 += z1[t] * (double)W2b[t * 10 + f];
            e2 += z2[t] * (double)W2b[t * 10 + f];
        }
        double b2 = e2 - ubar * a2;
        double s = sqrt(a2 * a2 * Vv + b2 * b2 * Vk + 2.0 * a2 * b2 * Cvk + BN_EPS);
        A2[f] = (double)g2[f] * a2 / s;
        B2[f] = (double)g2[f] * b2 / s;
    }
    double za[10], zb[10], zc[10];
    for (int t = 0; t < 10; t++) {
        double s1 = 0, s2 = 0, s3 = 0;
        for (int j = 0; j < 10; j++) {
            s1 += A2[j] * (double)W3a[j * 10 + t];
            s2 += B2[j] * (double)W3a[j * 10 + t];
            s3 += (double)be2[j] * (double)W3a[j * 10 + t];
        }
        za[t] = s1; zb[t] = s2; zc[t] = s3;
    }
    double A3[10], B3[10], C3[10];
    for (int f = 0; f < 10; f++) {
        double a3 = 0, b3 = 0, e3 = 0;
        for (int t = 0; t < 10; t++) {
            a3 += za[t] * (double)W3b[t * 10 + f];
            b3 += zb[t] * (double)W3b[t * 10 + f];
            e3 += zc[t] * (double)W3b[t * 10 + f];
        }
        double c3 = e3 - vbar * a3 - kbar * b3;
        double s = sqrt(a3 * a3 * Vp + b3 * b3 * Vm + c3 * c3 * Vk +
                        2.0 * a3 * b3 * Cpm + 2.0 * a3 * c3 * Cpk + 2.0 * b3 * c3 * Cmk + BN_EPS);
        A3[f] = (double)g3[f] * a3 / s;
        B3[f] = (double)g3[f] * b3 / s;
        C3[f] = (double)g3[f] * c3 / s;
    }
    for (int c = 0; c < 4; c++) {
        double lu = 0, lv = 0, lk = 0, lp = 0, lm = 0, l0 = (double)bf[c];
        for (int f = 0; f < 10; f++) {
            double wf1 = (double)Wf[f * 4 + c];
            double wf2 = (double)Wf[(10 + f) * 4 + c];
            double wf3 = (double)Wf[(20 + f) * 4 + c];
            lu += alpha1[f] * wf1;
            lv += A2[f] * wf2;
            lk += B2[f] * wf2 + C3[f] * wf3;
            lp += A3[f] * wf3;
            lm += B3[f] * wf3;
            l0 += (double)be1[f] * wf1 + (double)be2[f] * wf2 + (double)be3[f] * wf3;
        }
        g_coef.Lu[c] = (float)lu; g_coef.Lv[c] = (float)lv; g_coef.Lk[c] = (float)lk;
        g_coef.Lp[c] = (float)lp; g_coef.Lm[c] = (float)lm; g_coef.L0[c] = (float)l0;
    }
    g_coef.ubar = (float)ubar; g_coef.vbar = (float)vbar; g_coef.kbar = (float)kbar;
    g_coef.pbar = (float)pbar; g_coef.mbar = (float)mbar;
}

// ---------------- node pass 4: logits -> softmax -> s, and ds = deg @ s ----------------
__global__ void k_node4(float* __restrict__ out) {
    const float2* uk = reinterpret_cast<const float2*>(g_scratch + 6 * NN);
    const float* v = g_scratch + 8 * NN;
    const float* m = g_scratch + 9 * NN;
    const float* p = g_scratch + 10 * NN;
    const float* degw = g_scratch + 4 * NN;
    Coef c = g_coef;
    double d0 = 0, d1 = 0, d2 = 0, d3 = 0;
    int stride = gridDim.x * blockDim.x;
    for (int i = blockIdx.x * blockDim.x + threadIdx.x; i < NN; i += stride) {
        float2 ui = uk[i];
        float du = ui.x - c.ubar, dk = ui.y - c.kbar;
        float dv = v[i] - c.vbar;
        float dp = p[i] - c.pbar, dm = m[i] - c.mbar;
        float l0 = du * c.Lu[0] + dv * c.Lv[0] + dk * c.Lk[0] + dp * c.Lp[0] + dm * c.Lm[0] + c.L0[0];
        float l1 = du * c.Lu[1] + dv * c.Lv[1] + dk * c.Lk[1] + dp * c.Lp[1] + dm * c.Lm[1] + c.L0[1];
        float l2 = du * c.Lu[2] + dv * c.Lv[2] + dk * c.Lk[2] + dp * c.Lp[2] + dm * c.Lm[2] + c.L0[2];
        float l3 = du * c.Lu[3] + dv * c.Lv[3] + dk * c.Lk[3] + dp * c.Lp[3] + dm * c.Lm[3] + c.L0[3];
        float mx = fmaxf(fmaxf(l0, l1), fmaxf(l2, l3));
        float e0 = expf(l0 - mx), e1 = expf(l1 - mx), e2 = expf(l2 - mx), e3 = expf(l3 - mx);
        float inv = 1.0f / (e0 + e1 + e2 + e3);
        float4 sv = make_float4(e0 * inv, e1 * inv, e2 * inv, e3 * inv);
        reinterpret_cast<float4*>(out)[i] = sv;
        float dw = degw[i];
        d0 += (double)(dw * sv.x); d1 += (double)(dw * sv.y);
        d2 += (double)(dw * sv.z); d3 += (double)(dw * sv.w);
    }
    d0 = warp_red(d0); d1 = warp_red(d1); d2 = warp_red(d2); d3 = warp_red(d3);
    if ((threadIdx.x & 31) == 0) {
        atomicAdd(&g_stats.ds[0], d0); atomicAdd(&g_stats.ds[1], d1);
        atomicAdd(&g_stats.ds[2], d2); atomicAdd(&g_stats.ds[3], d3);
    }
}

// ---------------- edge pass 5: pos = sum_e w_e * dot(s[src], s[dst]) ----------------
__global__ void k_edge5(const float* __restrict__ w,
                        const float* __restrict__ out) {
    const float4* s4 = reinterpret_cast<const float4*>(out);
    double acc = 0.0;
    const int NQ = EE / 4;
    int stride = gridDim.x * blockDim.x;
    for (int q = blockIdx.x * blockDim.x + threadIdx.x; q < NQ; q += stride) {
        int4 a = __ldg(reinterpret_cast<const int4*>(g_idx) + 2 * q);
        int4 b = __ldg(reinterpret_cast<const int4*>(g_idx) + 2 * q + 1);
        float4 wv = __ldg(reinterpret_cast<const float4*>(w) + q);
        float4 A0 = __ldg(&s4[a.x]), B0 = __ldg(&s4[a.y]);
        float4 A1 = __ldg(&s4[a.z]), B1 = __ldg(&s4[a.w]);
        float4 A2 = __ldg(&s4[b.x]), B2 = __ldg(&s4[b.y]);
        float4 A3 = __ldg(&s4[b.z]), B3 = __ldg(&s4[b.w]);
        float t0 = wv.x * (A0.x * B0.x + A0.y * B0.y + A0.z * B0.z + A0.w * B0.w);
        float t1 = wv.y * (A1.x * B1.x + A1.y * B1.y + A1.z * B1.z + A1.w * B1.w);
        float t2 = wv.z * (A2.x * B2.x + A2.y * B2.y + A2.z * B2.z + A2.w * B2.w);
        float t3 = wv.w * (A3.x * B3.x + A3.y * B3.y + A3.z * B3.z + A3.w * B3.w);
        acc += (double)((t0 + t1) + (t2 + t3));
    }
    acc = warp_red(acc);
    if ((threadIdx.x & 31) == 0) atomicAdd(&g_stats.pos, acc);
}

// ---------------- final: q ----------------
__global__ void k_final(float* __restrict__ out) {
    double tm = g_stats.two_m;
    double q = g_stats.pos / tm;
#pragma unroll
    for (int c = 0; c < 4; c++) {
        double d = g_stats.ds[c] / tm;
        q -= d * d;
    }
    out[(size_t)4 * NN] = (float)q;
}

extern "C" void kernel_launch(void* const* d_in, const int* in_sizes, int n_in,
                              void* d_out, int out_size) {
    const float* x = (const float*)d_in[0];
    const void* ei = d_in[1];
    const float* w = (const float*)d_in[2];
    const float* W1a = (const float*)d_in[3];
    const float* W1b = (const float*)d_in[5];
    const float* g1 = (const float*)d_in[7];
    const float* be1 = (const float*)d_in[8];
    const float* W2a = (const float*)d_in[9];
    const float* W2b = (const float*)d_in[11];
    const float* g2 = (const float*)d_in[13];
    const float* be2 = (const float*)d_in[14];
    const float* W3a = (const float*)d_in[15];
    const float* W3b = (const float*)d_in[17];
    const float* g3 = (const float*)d_in[19];
    const float* be3 = (const float*)d_in[20];
    const float* Wf = (const float*)d_in[21];
    const float* bf = (const float*)d_in[22];
    float* out = (float*)d_out;

    const int ET = 256, EB = 1184;   // edge kernels
    const int NT = 256, NB = 592;    // node kernels

    k_detect<<<1, 256>>>(ei);
    k_zero<<<NB, NT>>>();
    k_edge1<<<EB, ET>>>(ei, x, w);
    k_node1<<<NB, NT>>>(x);
    k_edge2<<<EB, ET>>>();
    k_node2<<<NB, NT>>>();
    k_edge3<<<EB, ET>>>();
    k_node3<<<NB, NT>>>();
    k_coef<<<1, 32>>>(W1a, W1b, W2a, W2b, W3a, W3b, g1, be1, g2, be2, g3, be3, Wf, bf);
    k_node4<<<NB, NT>>>(out);
    k_edge5<<<EB, ET>>>(w, out);
    k_final<<<1, 1>>>(out);
}